// round 11
// baseline (speedup 1.0000x reference)
#include <cuda_runtime.h>

typedef unsigned long long ULL;

// ---------------- f32x2 helpers ----------------
__device__ __forceinline__ ULL pk2(float lo, float hi) {
    ULL r; asm("mov.b64 %0, {%1, %2};" : "=l"(r) : "f"(lo), "f"(hi)); return r;
}
__device__ __forceinline__ void upk2(ULL v, float& lo, float& hi) {
    asm("mov.b64 {%0, %1}, %2;" : "=f"(lo), "=f"(hi) : "l"(v));
}
__device__ __forceinline__ ULL ffma2(ULL a, ULL b, ULL c) {
    ULL d; asm("fma.rn.f32x2 %0, %1, %2, %3;" : "=l"(d) : "l"(a), "l"(b), "l"(c));
    return d;
}
__device__ __forceinline__ int remap48(int n) { return (n / 40) * 48 + (n % 40); }

// ---------------- scratch ----------------
__device__ float g_X [8*40*5*64*64];   // [b][c8*5+v][ar][h][w]

// ---------------- attn smem layout (floats) ----------------
#define PSS 388                  // P row stride: 388%32==4, mult of 4
#define VSS 404                  // V row stride: (5*404)%32==4, mult of 4
#define SM_PS   0                // Ps[64][388]=24832 ; Bs[64][320]=20480 overlays
#define SM_Q    24832            // Q[8][320]
#define SM_K    27392            // K[8][320]
#define SM_V    29952            // V[40][404] chunk48 = 16160
#define SM_W    46112            // Wsm[c][96]=6144 (Phase A); stage[2][2560] overlays (Phase B)
#define SM_RINV 52256            // [2][64] double-buffered
#define ATTN_SMEM_FLOATS 52384
#define ATTN_SMEM_BYTES  (ATTN_SMEM_FLOATS*4)

__global__ __launch_bounds__(1024)
void attn_kernel(const float* __restrict__ buffer,
                 const float* __restrict__ Wq, const float* __restrict__ Wk,
                 const float* __restrict__ Wv, const float* __restrict__ Wc)
{
    extern __shared__ float sm[];
    float* Bs  = sm;             // Phase A input, overlaid by Ps afterwards
    float* Wsm = sm + SM_W;      // [c][96]

    const int h    = blockIdx.x;
    const int b    = blockIdx.y;
    const int t    = threadIdx.x;
    const int lane = t & 31;
    const int wid  = t >> 5;     // 32 warps

    // ---- weights -> smem (transposed) ----
    for (int idx = t; idx < 96*64; idx += 1024) {
        int oc = idx >> 6, c = idx & 63;
        float v;
        if      (oc <  8) v = Wq[(oc      )*64 + c];
        else if (oc < 16) v = Wk[(oc -  8)*64 + c];
        else if (oc < 56) v = Wv[(oc - 16)*64 + c];
        else              v = Wc[(oc - 56)*64 + c];
        Wsm[c*96 + oc] = v;
    }
    // ---- buffer slice Bs[c][v*64+w] ----
    for (int f = t; f < 5120; f += 1024) {
        int r  = f >> 4;
        int w4 = f & 15;
        int c = r / 5, v = r % 5;
        float4 val = *(const float4*)(buffer + (((size_t)(b*64 + c)*5 + v)*4096 + h*64 + w4*4));
        *(float4*)(Bs + c*320 + v*64 + w4*4) = val;
    }
    __syncthreads();

    // ---- Phase A: [96oc x 64c] x [64c x 320n], 3 oc per warp ----
    {
        const int ocb = wid * 3;
        ULL acc[3][5];
        #pragma unroll
        for (int i = 0; i < 3; i++)
            #pragma unroll
            for (int jp = 0; jp < 5; jp++) acc[i][jp] = 0ull;

        for (int c = 0; c < 64; c++) {
            ULL w2[3];
            #pragma unroll
            for (int i = 0; i < 3; i++) {
                float wv = Wsm[c*96 + ocb + i];
                w2[i] = pk2(wv, wv);
            }
            #pragma unroll
            for (int jp = 0; jp < 5; jp++) {
                ULL b2 = *(const ULL*)(Bs + c*320 + 2*lane + 64*jp);
                #pragma unroll
                for (int i = 0; i < 3; i++) acc[i][jp] = ffma2(w2[i], b2, acc[i][jp]);
            }
        }
        #pragma unroll
        for (int i = 0; i < 3; i++) {
            int oc = ocb + i;
            #pragma unroll
            for (int jp = 0; jp < 5; jp++) {
                int n = 2*lane + 64*jp;
                if (oc < 8)       *(ULL*)(sm + SM_Q + oc*320 + n)               = acc[i][jp];
                else if (oc < 16) *(ULL*)(sm + SM_K + (oc-8)*320 + n)           = acc[i][jp];
                else if (oc < 56) *(ULL*)(sm + SM_V + (oc-16)*VSS + remap48(n)) = acc[i][jp];
                else {
                    int cc = oc - 56;          // c8*5 + ar
                    int c8 = cc / 5, ar = cc % 5;
                    float lo, hi; upk2(acc[i][jp], lo, hi);
                    size_t idx = ((((size_t)b*40 + c8*5 + jp)*5 + ar)*64 + h)*64 + 2*lane;
                    *(float2*)(g_X + idx) = make_float2(lo, hi);
                }
            }
        }
    }
    __syncthreads();

    // ---- Phase B: 5 tiles of 64 rows ----
    for (int tile = 0; tile < 5; tile++) {
        const int m0 = tile * 64;
        float* rinv = sm + SM_RINV + (tile & 1)*64;
        float* stg  = sm + SM_W    + (tile & 1)*2560;   // stage[row64][oc40]

        // B1: scores (scalar, inner dim 8) + softmax -> Ps (chunk48), rinv. 2 rows/warp.
        {
            float q[2][8];
            #pragma unroll
            for (int mi = 0; mi < 2; mi++)
                #pragma unroll
                for (int d = 0; d < 8; d++)
                    q[mi][d] = sm[SM_Q + d*320 + m0 + wid*2 + mi];

            float s[2][10];
            #pragma unroll
            for (int j = 0; j < 10; j++) {
                int n = lane + 32*j;
                float kv[8];
                #pragma unroll
                for (int d = 0; d < 8; d++) kv[d] = sm[SM_K + d*320 + n];
                #pragma unroll
                for (int mi = 0; mi < 2; mi++) {
                    float a = 0.f;
                    #pragma unroll
                    for (int d = 0; d < 8; d++) a += q[mi][d]*kv[d];
                    s[mi][j] = a;
                }
            }
            #pragma unroll
            for (int mi = 0; mi < 2; mi++) {
                float mx = s[mi][0];
                #pragma unroll
                for (int j = 1; j < 10; j++) mx = fmaxf(mx, s[mi][j]);
                #pragma unroll
                for (int o = 16; o; o >>= 1) mx = fmaxf(mx, __shfl_xor_sync(0xffffffffu, mx, o));
                float sum = 0.f;
                int r = wid*2 + mi;
                #pragma unroll
                for (int j = 0; j < 10; j++) {
                    float e = __expf(s[mi][j] - mx);
                    sum += e;
                    sm[SM_PS + r*PSS + remap48(lane + 32*j)] = e;
                }
                #pragma unroll
                for (int o = 16; o; o >>= 1) sum += __shfl_xor_sync(0xffffffffu, sum, o);
                if (lane == 0) rinv[r] = 1.0f / sum;
            }
        }
        __syncthreads();

        // B2: O[64][40] = P[64][320] * V^T  — LDS.128 hot loop
        // warp tile: 8 rows x 20 ocs; thread: 2 rows (ri*4+rowsub) x 5 ocs
        // n-split: l2 (in-warp, 2) x ws (warp pairs, 2) -> stage combine
        {
            const int l2     = lane & 1;        // in-warp n-split
            const int ocsub  = (lane >> 1) & 3; // 4 oc sub-blocks of 5
            const int rowsub = lane >> 3;       // row within group of 4
            const int ws     = wid & 1;         // cross-warp n-split
            const int oc_b   = (wid >> 1) & 1;  // 2 oc blocks of 20
            const int row_b  = wid >> 2;        // 8 row blocks of 8

            ULL acc[2][5];
            #pragma unroll
            for (int ri = 0; ri < 2; ri++)
                #pragma unroll
                for (int i = 0; i < 5; i++) acc[ri][i] = 0ull;

            const float* pbase = sm + SM_PS + (row_b*8 + rowsub)*PSS;  // + ri*4*PSS
            const float* vbase = sm + SM_V  + (oc_b*20 + ocsub*5)*VSS;

            #pragma unroll
            for (int phase = 0; phase < 2; phase++) {
                const int co = (l2 + 2*ws + 4*phase) * 48;     // chunk offset
                for (int jq = 0; jq < 10; jq++) {
                    ULL p2[2][2];
                    #pragma unroll
                    for (int ri = 0; ri < 2; ri++) {
                        ulonglong2 tp = *(const ulonglong2*)(pbase + ri*4*PSS + co + 4*jq);
                        p2[ri][0] = tp.x; p2[ri][1] = tp.y;
                    }
                    #pragma unroll
                    for (int i = 0; i < 5; i++) {
                        ulonglong2 tv = *(const ulonglong2*)(vbase + i*VSS + co + 4*jq);
                        #pragma unroll
                        for (int ri = 0; ri < 2; ri++) {
                            acc[ri][i] = ffma2(p2[ri][0], tv.x, acc[ri][i]);
                            acc[ri][i] = ffma2(p2[ri][1], tv.y, acc[ri][i]);
                        }
                    }
                }
            }

            // reduce in-warp l2 pair (xor 1)
            float red[2][5];
            #pragma unroll
            for (int ri = 0; ri < 2; ri++)
                #pragma unroll
                for (int i = 0; i < 5; i++) {
                    float lo, hi; upk2(acc[ri][i], lo, hi);
                    float a = lo + hi;
                    a += __shfl_xor_sync(0xffffffffu, a, 1);
                    red[ri][i] = a;
                }

            const int ocbase = oc_b*20 + ocsub*5;
            const int row    = row_b*8 + l2*4 + rowsub;   // thread owns ri = l2
            if (ws == 0) {
                #pragma unroll
                for (int i = 0; i < 5; i++)
                    stg[row*40 + ocbase + i] = red[l2][i];
            }
            __syncthreads();
            if (ws == 1) {
                float scale = rinv[row];
                #pragma unroll
                for (int i = 0; i < 5; i++) {
                    float val = red[l2][i] + stg[row*40 + ocbase + i];
                    int c8 = (ocbase + i) / 5, ar = (ocbase + i) % 5;
                    size_t idx = ((((size_t)b*40 + c8*5 + tile)*5 + ar)*64 + h)*64 + row;
                    g_X[idx] += scale * val;
                }
            }
        }
        // next B1 writes Ps only after the in-B2 barrier; rinv/stage parity-buffered.
    }
}

// ---------------- fused conv: per (b,h) CTA, conv1(+ReLU) -> smem Y1 -> conv2(+ReLU) ----------------
#define F_SM_X   0                      // Xs[40ci*5d][72], data at +3 = 14400
#define F_SM_W1  14400                  // W1s[(ci*7+kw)*66 + oc] = 18480
#define F_SM_Y   32880                  // Ys[(oc*5+d)*64 + w] = 20480
#define F_SM_W2  0                      // phase 2: W2s[(c*7+kd)*65 + oc] = 29120 (overlays X+W1)
#define F_SMEM_FLOATS 53360
#define F_SMEM_BYTES  (F_SMEM_FLOATS*4)

__global__ __launch_bounds__(1024)
void fused_conv_kernel(const float* __restrict__ W1, const float* __restrict__ W2,
                       float* __restrict__ out)
{
    extern __shared__ float sm[];
    float* Xs  = sm + F_SM_X;
    float* W1s = sm + F_SM_W1;
    float* Ys  = sm + F_SM_Y;
    float* W2s = sm + F_SM_W2;

    const int h = blockIdx.x, b = blockIdx.y;
    const int t = threadIdx.x;
    const int lane = t & 31;
    const int wid  = t >> 5;   // 32 warps

    // ---- phase 0: load X (all 5 d), W1 ----
    for (int idx = t; idx < 1200; idx += 1024) {          // zero pads
        int r = idx / 6, p = idx % 6;
        Xs[r*72 + (p < 3 ? p : 64 + p)] = 0.f;
    }
    for (int idx = t; idx < 12800; idx += 1024) {         // X rows: r = ci*5+d
        int r = idx >> 6, w = idx & 63;
        Xs[r*72 + 3 + w] = g_X[((size_t)(b*200 + r))*4096 + h*64 + w];
    }
    for (int idx = t; idx < 64*280; idx += 1024) {        // W1 transposed
        int oc = idx / 280, r = idx % 280;
        W1s[r*66 + oc] = W1[idx];
    }
    __syncthreads();

    // ---- phase 1: conv1 over W, ReLU -> Ys ----
    // 40 warp-tiles: tile tt -> d = tt/8, oc-block = (tt%8)*8. Two rounds.
    #pragma unroll
    for (int round = 0; round < 2; round++) {
        int tt = round*32 + wid;
        if (tt < 40) {
            int d = tt >> 3, ocb = (tt & 7) * 8;
            ULL acc[4][2];
            #pragma unroll
            for (int i = 0; i < 4; i++) { acc[i][0] = 0ull; acc[i][1] = 0ull; }

            for (int ci = 0; ci < 40; ci++) {
                const float* xr = Xs + (ci*5 + d)*72;
                #pragma unroll
                for (int kw = 0; kw < 7; kw++) {
                    float x0 = xr[lane + kw];
                    float x1 = xr[32 + lane + kw];
                    ULL xx0 = pk2(x0, x0), xx1 = pk2(x1, x1);
                    const float* wp = W1s + (ci*7+kw)*66 + ocb;
                    #pragma unroll
                    for (int i = 0; i < 4; i++) {
                        ULL w2 = *(const ULL*)(wp + 2*i);
                        acc[i][0] = ffma2(w2, xx0, acc[i][0]);
                        acc[i][1] = ffma2(w2, xx1, acc[i][1]);
                    }
                }
            }
            #pragma unroll
            for (int i = 0; i < 4; i++) {
                float a0lo, a0hi, a1lo, a1hi;
                upk2(acc[i][0], a0lo, a0hi);
                upk2(acc[i][1], a1lo, a1hi);
                int o0 = ((ocb + 2*i    )*5 + d)*64;
                int o1 = ((ocb + 2*i + 1)*5 + d)*64;
                Ys[o0 + lane]      = fmaxf(a0lo, 0.f);
                Ys[o1 + lane]      = fmaxf(a0hi, 0.f);
                Ys[o0 + 32 + lane] = fmaxf(a1lo, 0.f);
                Ys[o1 + 32 + lane] = fmaxf(a1hi, 0.f);
            }
        }
    }
    __syncthreads();

    // ---- load W2 (overlays X/W1 — safe after barrier) ----
    for (int idx = t; idx < 64*448; idx += 1024) {
        int o = idx / 448, r = idx % 448;
        W2s[r*65 + o] = W2[idx];
    }
    __syncthreads();

    // ---- phase 2: conv2 over D, ReLU -> out ----
    {
        const int oc = t >> 4, wg = t & 15;     // 4 w per thread
        ULL acc[5][2];
        #pragma unroll
        for (int d = 0; d < 5; d++) { acc[d][0] = 0ull; acc[d][1] = 0ull; }

        for (int c = 0; c < 64; c++) {
            ULL w2[7];
            #pragma unroll
            for (int kd = 0; kd < 7; kd++) {
                float wv = W2s[(c*7+kd)*65 + oc];
                w2[kd] = pk2(wv, wv);
            }
            #pragma unroll
            for (int dp = 0; dp < 5; dp++) {
                const float* yp = Ys + (c*5+dp)*64 + wg*4;
                ULL y20 = *(const ULL*)yp;
                ULL y21 = *(const ULL*)(yp + 2);
                #pragma unroll
                for (int d = 0; d < 5; d++) {
                    int kd = dp - d + 3;
                    if (kd < 0 || kd > 6) continue;     // compile-time pruned
                    acc[d][0] = ffma2(w2[kd], y20, acc[d][0]);
                    acc[d][1] = ffma2(w2[kd], y21, acc[d][1]);
                }
            }
        }
        #pragma unroll
        for (int d = 0; d < 5; d++) {
            size_t idx = (((size_t)b*64 + oc)*5 + d)*4096 + h*64 + wg*4;
            float lo0, hi0, lo1, hi1;
            upk2(acc[d][0], lo0, hi0);
            upk2(acc[d][1], lo1, hi1);
            *(float2*)(out + idx)     = make_float2(fmaxf(lo0, 0.f), fmaxf(hi0, 0.f));
            *(float2*)(out + idx + 2) = make_float2(fmaxf(lo1, 0.f), fmaxf(hi1, 0.f));
        }
    }
}

// ---------------- launch ----------------
extern "C" void kernel_launch(void* const* d_in, const int* in_sizes, int n_in,
                              void* d_out, int out_size)
{
    const float* buffer = (const float*)d_in[0];
    const float* Wq = (const float*)d_in[1];
    const float* Wk = (const float*)d_in[2];
    const float* Wv = (const float*)d_in[3];
    const float* Wc = (const float*)d_in[4];
    const float* W1 = (const float*)d_in[5];
    const float* W2 = (const float*)d_in[6];
    float* out = (float*)d_out;

    cudaFuncSetAttribute(attn_kernel,       cudaFuncAttributeMaxDynamicSharedMemorySize, ATTN_SMEM_BYTES);
    cudaFuncSetAttribute(fused_conv_kernel, cudaFuncAttributeMaxDynamicSharedMemorySize, F_SMEM_BYTES);

    attn_kernel      <<<dim3(64, 8), 1024, ATTN_SMEM_BYTES>>>(buffer, Wq, Wk, Wv, Wc);
    fused_conv_kernel<<<dim3(64, 8), 1024, F_SMEM_BYTES>>>(W1, W2, out);
}